// round 9
// baseline (speedup 1.0000x reference)
#include <cuda_runtime.h>
#include <cuda_bf16.h>
#include <math.h>

#define NB   256
#define HDIM 2048
#define QKVD 8192
#define QSZ  4096
#define TGT  4096
#define NC   32

// ---------------- scratch (no allocations allowed) ----------------
__device__ float g_core_base[NB * TGT];     // raw qkv-tail gemm output
__device__ float g_gate[NB * TGT];          // sigmoid(hidden @ Wgate^T)
__device__ float g_ab[NB * 64];             // [a(32) | b(32)] per batch
__device__ float g_core[NB * TGT];          // normalized gated core
__device__ float g_partial[4 * NB * HDIM];  // split-K partials

__device__ __forceinline__ float sigmoidf_(float x) { return 1.0f / (1.0f + expf(-x)); }

// ---------------- mma.sync bf16 plumbing ----------------
__device__ __forceinline__ void ldsm4(unsigned* r, unsigned addr) {
    asm volatile("ldmatrix.sync.aligned.m8n8.x4.shared.b16 {%0,%1,%2,%3}, [%4];"
                 : "=r"(r[0]), "=r"(r[1]), "=r"(r[2]), "=r"(r[3]) : "r"(addr));
}
#define MMA16816(d, a, b) asm volatile( \
    "mma.sync.aligned.m16n8k16.row.col.f32.bf16.bf16.f32 " \
    "{%0,%1,%2,%3}, {%4,%5,%6,%7}, {%8,%9}, {%0,%1,%2,%3};" \
    : "+f"((d)[0]), "+f"((d)[1]), "+f"((d)[2]), "+f"((d)[3]) \
    : "r"((a)[0]), "r"((a)[1]), "r"((a)[2]), "r"((a)[3]), "r"((b)[0]), "r"((b)[1]))

// split x into bf16 hi + bf16 lo (pairs packed into u32, low element first)
__device__ __forceinline__ void cvt2(float a, float b, unsigned& hi, unsigned& lo) {
    __nv_bfloat162 h = __floats2bfloat162_rn(a, b);
    float ra = a - __low2float(h);
    float rb = b - __high2float(h);
    __nv_bfloat162 l = __floats2bfloat162_rn(ra, rb);
    hi = *(unsigned*)&h;
    lo = *(unsigned*)&l;
}

// smem tile geometry: per plane 128 rows x 40 bf16 (pad 32->40 kills LDSM conflicts)
#define ROWSTR 40
#define PSTR   (128 * ROWSTR)           // elements per plane
#define SMEM_BYTES (2 * 4 * PSTR * 2)   // 2 bufs x 4 planes (Ahi,Alo,Bhi,Blo) x bf16

// =====================================================================
// K1: fused GEMM, M=256, K=2048. N-blocks: 0..31 qkv tail (raw ->
// g_core_base), 32..63 gate (sigmoid -> g_gate), 64 [Walpha;Wbeta] -> g_ab.
// BM=BN=128, BK=32, 8 warps (2x4), warp tile 64x32, bf16 hi/lo 3-pass mma.
// =====================================================================
__global__ void __launch_bounds__(256) k_gemm1(
    const float* __restrict__ A,       // hidden [256,2048]
    const float* __restrict__ Wqkv,    // [8192,2048]
    const float* __restrict__ Wgate,   // [4096,2048]
    const float* __restrict__ Walpha,  // [32,2048]
    const float* __restrict__ Wbeta)   // [32,2048]
{
    extern __shared__ __nv_bfloat16 smem[];
    const int tid  = threadIdx.x;
    const int m0   = blockIdx.y * 128;
    const int nblk = blockIdx.x;
    const int kind = (nblk < 32) ? 0 : (nblk < 64 ? 1 : 2);

    // per-thread global load slots: 4 chunks of float4 for A and B each
    const float* pA[4]; const float* pB[4]; int soff[4];
#pragma unroll
    for (int i = 0; i < 4; ++i) {
        int c = tid + i * 256;
        int r = c >> 3, kc = c & 7;
        soff[i] = r * ROWSTR + kc * 4;
        pA[i] = A + (size_t)(m0 + r) * HDIM + kc * 4;
        const float* rp;
        if (kind == 0)      rp = Wqkv  + (size_t)(QSZ + nblk * 128 + r) * HDIM;
        else if (kind == 1) rp = Wgate + (size_t)((nblk - 32) * 128 + r) * HDIM;
        else rp = (r < 32) ? Walpha + (size_t)r * HDIM
                 : (r < 64) ? Wbeta + (size_t)(r - 32) * HDIM
                            : Walpha + (size_t)(r & 31) * HDIM;   // dummy rows
        pB[i] = rp + kc * 4;
    }

    const unsigned sbase = (unsigned)__cvta_generic_to_shared(smem);
    const int lane = tid & 31, wid = tid >> 5;
    const int wm = wid >> 2, wn = wid & 3;

    float acc[4][4][4];
#pragma unroll
    for (int x = 0; x < 4; ++x)
#pragma unroll
        for (int y = 0; y < 4; ++y)
#pragma unroll
            for (int z = 0; z < 4; ++z) acc[x][y][z] = 0.f;

    // ldmatrix lane address components
    const int arow = wm * 64 + (lane & 15);
    const int akk  = (lane >> 4) << 3;
    const int brow = wn * 32 + ((lane >> 4) << 3) + (lane & 7);
    const int bkk  = ((lane >> 3) & 1) << 3;

    float4 ra[4], rb[4];
#pragma unroll
    for (int i = 0; i < 4; ++i) { ra[i] = *(const float4*)pA[i]; rb[i] = *(const float4*)pB[i]; }
    // store tile 0 into buf 0
#pragma unroll
    for (int i = 0; i < 4; ++i) {
        unsigned h0, l0, h1, l1;
        cvt2(ra[i].x, ra[i].y, h0, l0); cvt2(ra[i].z, ra[i].w, h1, l1);
        *(uint2*)(smem + 0 * PSTR + soff[i]) = make_uint2(h0, h1);
        *(uint2*)(smem + 1 * PSTR + soff[i]) = make_uint2(l0, l1);
        cvt2(rb[i].x, rb[i].y, h0, l0); cvt2(rb[i].z, rb[i].w, h1, l1);
        *(uint2*)(smem + 2 * PSTR + soff[i]) = make_uint2(h0, h1);
        *(uint2*)(smem + 3 * PSTR + soff[i]) = make_uint2(l0, l1);
    }
    __syncthreads();

    const int NT = HDIM / 32;
    int buf = 0;
    for (int t = 0; t < NT; ++t) {
        if (t + 1 < NT) {
#pragma unroll
            for (int i = 0; i < 4; ++i) {
                ra[i] = *(const float4*)(pA[i] + (t + 1) * 32);
                rb[i] = *(const float4*)(pB[i] + (t + 1) * 32);
            }
        }
        const unsigned pb = sbase + (unsigned)(buf * 4 * PSTR * 2);
#pragma unroll
        for (int ks = 0; ks < 2; ++ks) {
            const int koff = ks * 16;
            unsigned ah[4][4], al[4][4], bh[2][4], bl[2][4];
#pragma unroll
            for (int mf = 0; mf < 4; ++mf) {
                unsigned aoff = (unsigned)(((arow + mf * 16) * ROWSTR + akk + koff) * 2);
                ldsm4(ah[mf], pb + 0 * PSTR * 2 + aoff);
                ldsm4(al[mf], pb + 1 * PSTR * 2 + aoff);
            }
#pragma unroll
            for (int pr = 0; pr < 2; ++pr) {
                unsigned boff = (unsigned)(((brow + pr * 16) * ROWSTR + bkk + koff) * 2);
                ldsm4(bh[pr], pb + 2 * PSTR * 2 + boff);
                ldsm4(bl[pr], pb + 3 * PSTR * 2 + boff);
            }
#pragma unroll
            for (int mf = 0; mf < 4; ++mf)
#pragma unroll
                for (int nf = 0; nf < 4; ++nf) {
                    unsigned* bhp = &bh[nf >> 1][(nf & 1) * 2];
                    unsigned* blp = &bl[nf >> 1][(nf & 1) * 2];
                    MMA16816(acc[mf][nf], ah[mf], bhp);
                    MMA16816(acc[mf][nf], ah[mf], blp);
                    MMA16816(acc[mf][nf], al[mf], bhp);
                }
        }
        if (t + 1 < NT) {
            __nv_bfloat16* dst = smem + (buf ^ 1) * 4 * PSTR;
#pragma unroll
            for (int i = 0; i < 4; ++i) {
                unsigned h0, l0, h1, l1;
                cvt2(ra[i].x, ra[i].y, h0, l0); cvt2(ra[i].z, ra[i].w, h1, l1);
                *(uint2*)(dst + 0 * PSTR + soff[i]) = make_uint2(h0, h1);
                *(uint2*)(dst + 1 * PSTR + soff[i]) = make_uint2(l0, l1);
                cvt2(rb[i].x, rb[i].y, h0, l0); cvt2(rb[i].z, rb[i].w, h1, l1);
                *(uint2*)(dst + 2 * PSTR + soff[i]) = make_uint2(h0, h1);
                *(uint2*)(dst + 3 * PSTR + soff[i]) = make_uint2(l0, l1);
            }
        }
        __syncthreads();
        buf ^= 1;
    }

    // epilogue
    const int mb = m0 + wm * 64 + (lane >> 2);
    const int cb = wn * 32 + (lane & 3) * 2;
#pragma unroll
    for (int mf = 0; mf < 4; ++mf)
#pragma unroll
        for (int nf = 0; nf < 4; ++nf)
#pragma unroll
            for (int h = 0; h < 2; ++h) {
                int m = mb + mf * 16 + h * 8;
                int col = cb + nf * 8;
                float v0 = acc[mf][nf][h * 2], v1 = acc[mf][nf][h * 2 + 1];
                if (kind == 0) {
                    *(float2*)&g_core_base[(size_t)m * TGT + nblk * 128 + col] = make_float2(v0, v1);
                } else if (kind == 1) {
                    *(float2*)&g_gate[(size_t)m * TGT + (nblk - 32) * 128 + col] =
                        make_float2(sigmoidf_(v0), sigmoidf_(v1));
                } else if (col < 64) {
                    *(float2*)&g_ab[(size_t)m * 64 + col] = make_float2(v0, v1);
                }
            }
}

// =====================================================================
// K2: per-batch fused conv + SSM + RMS + gate. 1 CTA per batch row.
// All global traffic coalesced; conv moved here from the GEMM epilogue.
// =====================================================================
__global__ void __launch_bounds__(256) k_fuse(
    const float* __restrict__ bqkv,
    const float* __restrict__ convk,    // [8192,4]
    const float* __restrict__ convst,   // [256,4,8192]
    const float* __restrict__ ssa,
    const float* __restrict__ dtb,
    const float* __restrict__ normw,
    const float* __restrict__ sstate)
{
    __shared__ float s_conv[TGT];
    __shared__ float kg[NC], vg[NC], ssig[NC], red[8];
    __shared__ float s_scale, s_wmean;
    const int b = blockIdx.x, tid = threadIdx.x;
    const int lane = tid & 31, w = tid >> 5;

#pragma unroll
    for (int i = 0; i < 16; ++i) {
        int idx = tid + i * 256;
        int d = QSZ + idx;
        float val = g_core_base[(size_t)b * TGT + idx] + bqkv[d];
        float4 ck = *(const float4*)(convk + (size_t)d * 4);
        float co = val * ck.w
                 + convst[((size_t)b * 4 + 1) * QKVD + d] * ck.x
                 + convst[((size_t)b * 4 + 2) * QKVD + d] * ck.y
                 + convst[((size_t)b * 4 + 3) * QKVD + d] * ck.z;
        s_conv[idx] = co;
    }
    if (tid == 0) {
        float wm = 0.f;
        for (int i = 0; i < 128; ++i) wm += normw[i];
        s_wmean = wm * (1.0f / 128.0f);
    }
    __syncthreads();

    {   // 64 group means of 64 elements, 4 threads per group
        int gg = tid >> 2, sub = tid & 3;
        const float* p = s_conv + gg * 64 + sub * 16;
        float s = 0.f;
#pragma unroll
        for (int i = 0; i < 16; ++i) s += p[i];
        s += __shfl_xor_sync(0xFFFFFFFFu, s, 1);
        s += __shfl_xor_sync(0xFFFFFFFFu, s, 2);
        if (sub == 0) {
            float mn = s * (1.0f / 64.0f);
            if (gg < NC) kg[gg] = mn; else vg[gg - NC] = mn;
        }
    }
    __syncthreads();

    if (tid < NC) {
        int c = tid;
        float av = g_ab[(size_t)b * 64 + c];
        float bv = g_ab[(size_t)b * 64 + 32 + c];
        float x  = av + dtb[c];
        float sp = (x > 20.f) ? x : log1pf(expf(x));
        float g  = -expf(ssa[c]) * sp;
        float ns = expf(g) * sstate[(size_t)b * NC + c] + sigmoidf_(bv) * vg[c];
        ssig[c]  = ns * sigmoidf_(kg[c]);
    }
    __syncthreads();

    float cv[16]; float sq = 0.f;
#pragma unroll
    for (int i = 0; i < 16; ++i) {
        int idx = tid + i * 256;
        float v = s_conv[idx] + ssig[idx >> 7];
        cv[i] = v; sq += v * v;
    }
#pragma unroll
    for (int o = 16; o; o >>= 1) sq += __shfl_xor_sync(0xFFFFFFFFu, sq, o);
    if (lane == 0) red[w] = sq;
    __syncthreads();
    if (tid == 0) {
        float t = 0.f;
        for (int i = 0; i < 8; ++i) t += red[i];
        s_scale = rsqrtf(t * (1.0f / (float)TGT) + 1e-6f);
    }
    __syncthreads();

    const float scl = s_scale * s_wmean;
#pragma unroll
    for (int i = 0; i < 16; ++i) {
        int idx = tid + i * 256;
        g_core[(size_t)b * TGT + idx] = cv[i] * scl * g_gate[(size_t)b * TGT + idx];
    }
}

// =====================================================================
// K3: out GEMM [256,2048] = g_core[256,4096] @ Wout[2048,4096]^T,
// split-K=4 (blockIdx.z), same bf16 hi/lo 3-pass engine.
// =====================================================================
__global__ void __launch_bounds__(256) k_gemm2(const float* __restrict__ Wout)
{
    extern __shared__ __nv_bfloat16 smem[];
    const int tid = threadIdx.x;
    const int m0  = blockIdx.y * 128;
    const int n0  = blockIdx.x * 128;
    const int s   = blockIdx.z;
    const int kbeg = s * 1024;

    const float* pA[4]; const float* pB[4]; int soff[4];
#pragma unroll
    for (int i = 0; i < 4; ++i) {
        int c = tid + i * 256;
        int r = c >> 3, kc = c & 7;
        soff[i] = r * ROWSTR + kc * 4;
        pA[i] = g_core + (size_t)(m0 + r) * TGT + kbeg + kc * 4;
        pB[i] = Wout   + (size_t)(n0 + r) * TGT + kbeg + kc * 4;
    }

    const unsigned sbase = (unsigned)__cvta_generic_to_shared(smem);
    const int lane = tid & 31, wid = tid >> 5;
    const int wm = wid >> 2, wn = wid & 3;

    float acc[4][4][4];
#pragma unroll
    for (int x = 0; x < 4; ++x)
#pragma unroll
        for (int y = 0; y < 4; ++y)
#pragma unroll
            for (int z = 0; z < 4; ++z) acc[x][y][z] = 0.f;

    const int arow = wm * 64 + (lane & 15);
    const int akk  = (lane >> 4) << 3;
    const int brow = wn * 32 + ((lane >> 4) << 3) + (lane & 7);
    const int bkk  = ((lane >> 3) & 1) << 3;

    float4 ra[4], rb[4];
#pragma unroll
    for (int i = 0; i < 4; ++i) { ra[i] = *(const float4*)pA[i]; rb[i] = *(const float4*)pB[i]; }
#pragma unroll
    for (int i = 0; i < 4; ++i) {
        unsigned h0, l0, h1, l1;
        cvt2(ra[i].x, ra[i].y, h0, l0); cvt2(ra[i].z, ra[i].w, h1, l1);
        *(uint2*)(smem + 0 * PSTR + soff[i]) = make_uint2(h0, h1);
        *(uint2*)(smem + 1 * PSTR + soff[i]) = make_uint2(l0, l1);
        cvt2(rb[i].x, rb[i].y, h0, l0); cvt2(rb[i].z, rb[i].w, h1, l1);
        *(uint2*)(smem + 2 * PSTR + soff[i]) = make_uint2(h0, h1);
        *(uint2*)(smem + 3 * PSTR + soff[i]) = make_uint2(l0, l1);
    }
    __syncthreads();

    const int NT = 1024 / 32;
    int buf = 0;
    for (int t = 0; t < NT; ++t) {
        if (t + 1 < NT) {
#pragma unroll
            for (int i = 0; i < 4; ++i) {
                ra[i] = *(const float4*)(pA[i] + (t + 1) * 32);
                rb[i] = *(const float4*)(pB[i] + (t + 1) * 32);
            }
        }
        const unsigned pb = sbase + (unsigned)(buf * 4 * PSTR * 2);
#pragma unroll
        for (int ks = 0; ks < 2; ++ks) {
            const int koff = ks * 16;
            unsigned ah[4][4], al[4][4], bh[2][4], bl[2][4];
#pragma unroll
            for (int mf = 0; mf < 4; ++mf) {
                unsigned aoff = (unsigned)(((arow + mf * 16) * ROWSTR + akk + koff) * 2);
                ldsm4(ah[mf], pb + 0 * PSTR * 2 + aoff);
                ldsm4(al[mf], pb + 1 * PSTR * 2 + aoff);
            }
#pragma unroll
            for (int pr = 0; pr < 2; ++pr) {
                unsigned boff = (unsigned)(((brow + pr * 16) * ROWSTR + bkk + koff) * 2);
                ldsm4(bh[pr], pb + 2 * PSTR * 2 + boff);
                ldsm4(bl[pr], pb + 3 * PSTR * 2 + boff);
            }
#pragma unroll
            for (int mf = 0; mf < 4; ++mf)
#pragma unroll
                for (int nf = 0; nf < 4; ++nf) {
                    unsigned* bhp = &bh[nf >> 1][(nf & 1) * 2];
                    unsigned* blp = &bl[nf >> 1][(nf & 1) * 2];
                    MMA16816(acc[mf][nf], ah[mf], bhp);
                    MMA16816(acc[mf][nf], ah[mf], blp);
                    MMA16816(acc[mf][nf], al[mf], bhp);
                }
        }
        if (t + 1 < NT) {
            __nv_bfloat16* dst = smem + (buf ^ 1) * 4 * PSTR;
#pragma unroll
            for (int i = 0; i < 4; ++i) {
                unsigned h0, l0, h1, l1;
                cvt2(ra[i].x, ra[i].y, h0, l0); cvt2(ra[i].z, ra[i].w, h1, l1);
                *(uint2*)(dst + 0 * PSTR + soff[i]) = make_uint2(h0, h1);
                *(uint2*)(dst + 1 * PSTR + soff[i]) = make_uint2(l0, l1);
                cvt2(rb[i].x, rb[i].y, h0, l0); cvt2(rb[i].z, rb[i].w, h1, l1);
                *(uint2*)(dst + 2 * PSTR + soff[i]) = make_uint2(h0, h1);
                *(uint2*)(dst + 3 * PSTR + soff[i]) = make_uint2(l0, l1);
            }
        }
        __syncthreads();
        buf ^= 1;
    }

    float* part = g_partial + (size_t)s * NB * HDIM;
    const int mb = m0 + wm * 64 + (lane >> 2);
    const int cb = n0 + wn * 32 + (lane & 3) * 2;
#pragma unroll
    for (int mf = 0; mf < 4; ++mf)
#pragma unroll
        for (int nf = 0; nf < 4; ++nf)
#pragma unroll
            for (int h = 0; h < 2; ++h) {
                int m = mb + mf * 16 + h * 8;
                int col = cb + nf * 8;
                *(float2*)&part[(size_t)m * HDIM + col] =
                    make_float2(acc[mf][nf][h * 2], acc[mf][nf][h * 2 + 1]);
            }
}

// K4: sum split-K partials -> d_out (vectorized)
__global__ void __launch_bounds__(256) k_reduce(float4* __restrict__ out)
{
    int i = blockIdx.x * 256 + threadIdx.x;
    const float4* p = (const float4*)g_partial;
    const int st = NB * HDIM / 4;
    float4 a = p[i], b = p[i + st], c = p[i + 2 * st], d = p[i + 3 * st];
    out[i] = make_float4(a.x + b.x + c.x + d.x, a.y + b.y + c.y + d.y,
                         a.z + b.z + c.z + d.z, a.w + b.w + c.w + d.w);
}

// =====================================================================
extern "C" void kernel_launch(void* const* d_in, const int* in_sizes, int n_in,
                              void* d_out, int out_size)
{
    (void)in_sizes; (void)n_in; (void)out_size;
    const float* hidden = (const float*)d_in[0];
    const float* Wqkv   = (const float*)d_in[1];
    const float* bqkv   = (const float*)d_in[2];
    const float* Wgate  = (const float*)d_in[3];
    const float* Walpha = (const float*)d_in[4];
    const float* Wbeta  = (const float*)d_in[5];
    const float* Wout   = (const float*)d_in[6];
    const float* ssa    = (const float*)d_in[7];
    const float* dtb    = (const float*)d_in[8];
    const float* normw  = (const float*)d_in[9];
    const float* convk  = (const float*)d_in[10];
    const float* sstate = (const float*)d_in[11];
    const float* convst = (const float*)d_in[12];
    float* out = (float*)d_out;

    cudaFuncSetAttribute(k_gemm1, cudaFuncAttributeMaxDynamicSharedMemorySize, SMEM_BYTES);
    cudaFuncSetAttribute(k_gemm2, cudaFuncAttributeMaxDynamicSharedMemorySize, SMEM_BYTES);

    k_gemm1<<<dim3(65, 2), 256, SMEM_BYTES>>>(hidden, Wqkv, Wgate, Walpha, Wbeta);
    k_fuse <<<NB, 256>>>(bqkv, convk, convst, ssa, dtb, normw, sstate);
    k_gemm2<<<dim3(16, 2, 4), 256, SMEM_BYTES>>>(Wout);
    k_reduce<<<(NB * HDIM / 4) / 256, 256>>>((float4*)out);
}

// round 12
// speedup vs baseline: 1.0101x; 1.0101x over previous
#include <cuda_runtime.h>
#include <cuda_fp16.h>
#include <math.h>

#define NB   256
#define HDIM 2048
#define QKVD 8192
#define QSZ  4096
#define TGT  4096
#define NC   32

// ---------------- scratch (no allocations allowed) ----------------
__device__ float g_core_base[NB * TGT];     // raw qkv-tail gemm output
__device__ float g_gate[NB * TGT];          // sigmoid(hidden @ Wgate^T)
__device__ float g_ab[NB * 64];             // [a(32) | b(32)] per batch
__device__ float g_core[NB * TGT];          // normalized gated core

__device__ __forceinline__ float sigmoidf_(float x) { return 1.0f / (1.0f + expf(-x)); }

// ---------------- mma.sync fp16 plumbing ----------------
__device__ __forceinline__ void ldsm4(unsigned* r, unsigned addr) {
    asm volatile("ldmatrix.sync.aligned.m8n8.x4.shared.b16 {%0,%1,%2,%3}, [%4];"
                 : "=r"(r[0]), "=r"(r[1]), "=r"(r[2]), "=r"(r[3]) : "r"(addr));
}
#define MMA16816(d, a, b) asm volatile( \
    "mma.sync.aligned.m16n8k16.row.col.f32.f16.f16.f32 " \
    "{%0,%1,%2,%3}, {%4,%5,%6,%7}, {%8,%9}, {%0,%1,%2,%3};" \
    : "+f"((d)[0]), "+f"((d)[1]), "+f"((d)[2]), "+f"((d)[3]) \
    : "r"((a)[0]), "r"((a)[1]), "r"((a)[2]), "r"((a)[3]), "r"((b)[0]), "r"((b)[1]))

// split x into fp16 hi + fp16 lo (pairs packed into u32, low element first)
__device__ __forceinline__ void cvt2(float a, float b, unsigned& hi, unsigned& lo) {
    __half2 h = __floats2half2_rn(a, b);
    float ra = a - __low2float(h);
    float rb = b - __high2float(h);
    __half2 l = __floats2half2_rn(ra, rb);
    hi = *(unsigned*)&h;
    lo = *(unsigned*)&l;
}

// smem tile geometry: per plane 128 rows x 40 fp16 (pad 32->40 kills LDSM conflicts)
#define ROWSTR 40
#define PSTR   (128 * ROWSTR)           // elements per plane
#define SMEM_BYTES (2 * 4 * PSTR * 2)   // 2 bufs x 4 planes (Ahi,Alo,Bhi,Blo) x fp16

// =====================================================================
// K1: fused GEMM over N = [qkv tail | gate | alpha/beta], M=256, K=2048.
// BM=BN=128, BK=32, 8 warps (2x4), warp tile 64x32, fp16 hi/lo mma.
// Gate blocks (kind==1) use 2-pass (drop A_lo*B_hi); others 3-pass.
// =====================================================================
__global__ void __launch_bounds__(256) k_gemm1(
    const float* __restrict__ A,       // hidden [256,2048]
    const float* __restrict__ Wqkv,    // [8192,2048]
    const float* __restrict__ Wgate,   // [4096,2048]
    const float* __restrict__ Walpha,  // [32,2048]
    const float* __restrict__ Wbeta)   // [32,2048]
{
    extern __shared__ __half smem[];
    const int tid  = threadIdx.x;
    const int m0   = blockIdx.y * 128;
    const int nblk = blockIdx.x;
    const int kind = (nblk < 32) ? 0 : (nblk < 64 ? 1 : 2);
    const bool three = (kind != 1);    // 3rd pass only for non-gate blocks

    const float* pA[4]; const float* pB[4]; int soff[4];
#pragma unroll
    for (int i = 0; i < 4; ++i) {
        int c = tid + i * 256;
        int r = c >> 3, kc = c & 7;
        soff[i] = r * ROWSTR + kc * 4;
        pA[i] = A + (size_t)(m0 + r) * HDIM + kc * 4;
        const float* rp;
        if (kind == 0)      rp = Wqkv  + (size_t)(QSZ + nblk * 128 + r) * HDIM;
        else if (kind == 1) rp = Wgate + (size_t)((nblk - 32) * 128 + r) * HDIM;
        else rp = (r < 32) ? Walpha + (size_t)r * HDIM
                 : (r < 64) ? Wbeta + (size_t)(r - 32) * HDIM
                            : Walpha + (size_t)(r & 31) * HDIM;   // dummy rows
        pB[i] = rp + kc * 4;
    }

    const unsigned sbase = (unsigned)__cvta_generic_to_shared(smem);
    const int lane = tid & 31, wid = tid >> 5;
    const int wm = wid >> 2, wn = wid & 3;

    float acc[4][4][4];
#pragma unroll
    for (int x = 0; x < 4; ++x)
#pragma unroll
        for (int y = 0; y < 4; ++y)
#pragma unroll
            for (int z = 0; z < 4; ++z) acc[x][y][z] = 0.f;

    const int arow = wm * 64 + (lane & 15);
    const int akk  = (lane >> 4) << 3;
    const int brow = wn * 32 + ((lane >> 4) << 3) + (lane & 7);
    const int bkk  = ((lane >> 3) & 1) << 3;

    float4 ra[4], rb[4];
#pragma unroll
    for (int i = 0; i < 4; ++i) { ra[i] = *(const float4*)pA[i]; rb[i] = *(const float4*)pB[i]; }
#pragma unroll
    for (int i = 0; i < 4; ++i) {
        unsigned h0, l0, h1, l1;
        cvt2(ra[i].x, ra[i].y, h0, l0); cvt2(ra[i].z, ra[i].w, h1, l1);
        *(uint2*)(smem + 0 * PSTR + soff[i]) = make_uint2(h0, h1);
        *(uint2*)(smem + 1 * PSTR + soff[i]) = make_uint2(l0, l1);
        cvt2(rb[i].x, rb[i].y, h0, l0); cvt2(rb[i].z, rb[i].w, h1, l1);
        *(uint2*)(smem + 2 * PSTR + soff[i]) = make_uint2(h0, h1);
        *(uint2*)(smem + 3 * PSTR + soff[i]) = make_uint2(l0, l1);
    }
    __syncthreads();

    const int NT = HDIM / 32;
    int buf = 0;
    for (int t = 0; t < NT; ++t) {
        if (t + 1 < NT) {
#pragma unroll
            for (int i = 0; i < 4; ++i) {
                ra[i] = *(const float4*)(pA[i] + (t + 1) * 32);
                rb[i] = *(const float4*)(pB[i] + (t + 1) * 32);
            }
        }
        const unsigned pb = sbase + (unsigned)(buf * 4 * PSTR * 2);
#pragma unroll
        for (int ks = 0; ks < 2; ++ks) {
            const int koff = ks * 16;
            unsigned ah[4][4], al[4][4], bh[2][4], bl[2][4];
#pragma unroll
            for (int mf = 0; mf < 4; ++mf) {
                unsigned aoff = (unsigned)(((arow + mf * 16) * ROWSTR + akk + koff) * 2);
                ldsm4(ah[mf], pb + 0 * PSTR * 2 + aoff);
                if (three) ldsm4(al[mf], pb + 1 * PSTR * 2 + aoff);
            }
#pragma unroll
            for (int pr = 0; pr < 2; ++pr) {
                unsigned boff = (unsigned)(((brow + pr * 16) * ROWSTR + bkk + koff) * 2);
                ldsm4(bh[pr], pb + 2 * PSTR * 2 + boff);
                ldsm4(bl[pr], pb + 3 * PSTR * 2 + boff);
            }
#pragma unroll
            for (int mf = 0; mf < 4; ++mf)
#pragma unroll
                for (int nf = 0; nf < 4; ++nf) {
                    unsigned* bhp = &bh[nf >> 1][(nf & 1) * 2];
                    unsigned* blp = &bl[nf >> 1][(nf & 1) * 2];
                    MMA16816(acc[mf][nf], ah[mf], bhp);
                    MMA16816(acc[mf][nf], ah[mf], blp);
                    if (three) MMA16816(acc[mf][nf], al[mf], bhp);
                }
        }
        if (t + 1 < NT) {
            __half* dst = smem + (buf ^ 1) * 4 * PSTR;
#pragma unroll
            for (int i = 0; i < 4; ++i) {
                unsigned h0, l0, h1, l1;
                cvt2(ra[i].x, ra[i].y, h0, l0); cvt2(ra[i].z, ra[i].w, h1, l1);
                *(uint2*)(dst + 0 * PSTR + soff[i]) = make_uint2(h0, h1);
                *(uint2*)(dst + 1 * PSTR + soff[i]) = make_uint2(l0, l1);
                cvt2(rb[i].x, rb[i].y, h0, l0); cvt2(rb[i].z, rb[i].w, h1, l1);
                *(uint2*)(dst + 2 * PSTR + soff[i]) = make_uint2(h0, h1);
                *(uint2*)(dst + 3 * PSTR + soff[i]) = make_uint2(l0, l1);
            }
        }
        __syncthreads();
        buf ^= 1;
    }

    // epilogue
    const int mb = m0 + wm * 64 + (lane >> 2);
    const int cb = wn * 32 + (lane & 3) * 2;
#pragma unroll
    for (int mf = 0; mf < 4; ++mf)
#pragma unroll
        for (int nf = 0; nf < 4; ++nf)
#pragma unroll
            for (int h = 0; h < 2; ++h) {
                int m = mb + mf * 16 + h * 8;
                int col = cb + nf * 8;
                float v0 = acc[mf][nf][h * 2], v1 = acc[mf][nf][h * 2 + 1];
                if (kind == 0) {
                    *(float2*)&g_core_base[(size_t)m * TGT + nblk * 128 + col] = make_float2(v0, v1);
                } else if (kind == 1) {
                    *(float2*)&g_gate[(size_t)m * TGT + (nblk - 32) * 128 + col] =
                        make_float2(sigmoidf_(v0), sigmoidf_(v1));
                } else if (col < 64) {
                    *(float2*)&g_ab[(size_t)m * 64 + col] = make_float2(v0, v1);
                }
            }
}

// =====================================================================
// K2: per-batch fused conv + SSM + RMS + gate; also zeroes d_out so the
// out-GEMM can accumulate with atomics. 1 CTA per batch row.
// =====================================================================
__global__ void __launch_bounds__(256) k_fuse(
    const float* __restrict__ bqkv,
    const float* __restrict__ convk,    // [8192,4]
    const float* __restrict__ convst,   // [256,4,8192]
    const float* __restrict__ ssa,
    const float* __restrict__ dtb,
    const float* __restrict__ normw,
    const float* __restrict__ sstate,
    float* __restrict__ out)            // [256,2048] -> zeroed here
{
    __shared__ float s_conv[TGT];
    __shared__ float kg[NC], vg[NC], ssig[NC], red[8];
    __shared__ float s_scale, s_wmean;
    const int b = blockIdx.x, tid = threadIdx.x;
    const int lane = tid & 31, w = tid >> 5;

    // zero this batch row of the output (atomic accumulation target)
#pragma unroll
    for (int i = 0; i < 8; ++i) out[(size_t)b * HDIM + tid + i * 256] = 0.f;

#pragma unroll
    for (int i = 0; i < 16; ++i) {
        int idx = tid + i * 256;
        int d = QSZ + idx;
        float val = g_core_base[(size_t)b * TGT + idx] + bqkv[d];
        float4 ck = *(const float4*)(convk + (size_t)d * 4);
        float co = val * ck.w
                 + convst[((size_t)b * 4 + 1) * QKVD + d] * ck.x
                 + convst[((size_t)b * 4 + 2) * QKVD + d] * ck.y
                 + convst[((size_t)b * 4 + 3) * QKVD + d] * ck.z;
        s_conv[idx] = co;
    }
    if (tid == 0) {
        float wm = 0.f;
        for (int i = 0; i < 128; ++i) wm += normw[i];
        s_wmean = wm * (1.0f / 128.0f);
    }
    __syncthreads();

    {   // 64 group means of 64 elements, 4 threads per group
        int gg = tid >> 2, sub = tid & 3;
        const float* p = s_conv + gg * 64 + sub * 16;
        float s = 0.f;
#pragma unroll
        for (int i = 0; i < 16; ++i) s += p[i];
        s += __shfl_xor_sync(0xFFFFFFFFu, s, 1);
        s += __shfl_xor_sync(0xFFFFFFFFu, s, 2);
        if (sub == 0) {
            float mn = s * (1.0f / 64.0f);
            if (gg < NC) kg[gg] = mn; else vg[gg - NC] = mn;
        }
    }
    __syncthreads();

    if (tid < NC) {
        int c = tid;
        float av = g_ab[(size_t)b * 64 + c];
        float bv = g_ab[(size_t)b * 64 + 32 + c];
        float x  = av + dtb[c];
        float sp = (x > 20.f) ? x : log1pf(expf(x));
        float g  = -expf(ssa[c]) * sp;
        float ns = expf(g) * sstate[(size_t)b * NC + c] + sigmoidf_(bv) * vg[c];
        ssig[c]  = ns * sigmoidf_(kg[c]);
    }
    __syncthreads();

    float cv[16]; float sq = 0.f;
#pragma unroll
    for (int i = 0; i < 16; ++i) {
        int idx = tid + i * 256;
        float v = s_conv[idx] + ssig[idx >> 7];
        cv[i] = v; sq += v * v;
    }
#pragma unroll
    for (int o = 16; o; o >>= 1) sq += __shfl_xor_sync(0xFFFFFFFFu, sq, o);
    if (lane == 0) red[w] = sq;
    __syncthreads();
    if (tid == 0) {
        float t = 0.f;
        for (int i = 0; i < 8; ++i) t += red[i];
        s_scale = rsqrtf(t * (1.0f / (float)TGT) + 1e-6f);
    }
    __syncthreads();

    const float scl = s_scale * s_wmean;
#pragma unroll
    for (int i = 0; i < 16; ++i) {
        int idx = tid + i * 256;
        g_core[(size_t)b * TGT + idx] = cv[i] * scl * g_gate[(size_t)b * TGT + idx];
    }
}

// =====================================================================
// K3: out GEMM [256,2048] = g_core[256,4096] @ Wout[2048,4096]^T,
// split-K=4 (blockIdx.z), fp16 hi/lo 3-pass, atomicAdd epilogue -> d_out.
// =====================================================================
__global__ void __launch_bounds__(256) k_gemm2(const float* __restrict__ Wout,
                                               float* __restrict__ out)
{
    extern __shared__ __half smem[];
    const int tid = threadIdx.x;
    const int m0  = blockIdx.y * 128;
    const int n0  = blockIdx.x * 128;
    const int s   = blockIdx.z;
    const int kbeg = s * 1024;

    const float* pA[4]; const float* pB[4]; int soff[4];
#pragma unroll
    for (int i = 0; i < 4; ++i) {
        int c = tid + i * 256;
        int r = c >> 3, kc = c & 7;
        soff[i] = r * ROWSTR + kc * 4;
        pA[i] = g_core + (size_t)(m0 + r) * TGT + kbeg + kc * 4;
        pB[i] = Wout   + (size_t)(n0 + r) * TGT + kbeg + kc * 4;
    }

    const unsigned sbase = (unsigned)__cvta_generic_to_shared(smem);
    const int lane = tid & 31, wid = tid >> 5;
    const int wm = wid >> 2, wn = wid & 3;

    float acc[4][4][4];
#pragma unroll
    for (int x = 0; x < 4; ++x)
#pragma unroll
        for (int y = 0; y < 4; ++y)
#pragma unroll
            for (int z = 0; z < 4; ++z) acc[x][y][z] = 0.f;

    const int arow = wm * 64 + (lane & 15);
    const int akk  = (lane >> 4) << 3;
    const int brow = wn * 32 + ((lane >> 4) << 3) + (lane & 7);
    const int bkk  = ((lane >> 3) & 1) << 3;

    float4 ra[4], rb[4];
#pragma unroll
    for (int i = 0; i < 4; ++i) { ra[i] = *(const float4*)pA[i]; rb[i] = *(const float4*)pB[i]; }
#pragma unroll
    for (int i = 0; i < 4; ++i) {
        unsigned h0, l0, h1, l1;
        cvt2(ra[i].x, ra[i].y, h0, l0); cvt2(ra[i].z, ra[i].w, h1, l1);
        *(uint2*)(smem + 0 * PSTR + soff[i]) = make_uint2(h0, h1);
        *(uint2*)(smem + 1 * PSTR + soff[i]) = make_uint2(l0, l1);
        cvt2(rb[i].x, rb[i].y, h0, l0); cvt2(rb[i].z, rb[i].w, h1, l1);
        *(uint2*)(smem + 2 * PSTR + soff[i]) = make_uint2(h0, h1);
        *(uint2*)(smem + 3 * PSTR + soff[i]) = make_uint2(l0, l1);
    }
    __syncthreads();

    const int NT = 1024 / 32;
    int buf = 0;
    for (int t = 0; t < NT; ++t) {
        if (t + 1 < NT) {
#pragma unroll
            for (int i = 0; i < 4; ++i) {
                ra[i] = *(const float4*)(pA[i] + (t + 1) * 32);
                rb[i] = *(const float4*)(pB[i] + (t + 1) * 32);
            }
        }
        const unsigned pb = sbase + (unsigned)(buf * 4 * PSTR * 2);
#pragma unroll
        for (int ks = 0; ks < 2; ++ks) {
            const int koff = ks * 16;
            unsigned ah[4][4], al[4][4], bh[2][4], bl[2][4];
#pragma unroll
            for (int mf = 0; mf < 4; ++mf) {
                unsigned aoff = (unsigned)(((arow + mf * 16) * ROWSTR + akk + koff) * 2);
                ldsm4(ah[mf], pb + 0 * PSTR * 2 + aoff);
                ldsm4(al[mf], pb + 1 * PSTR * 2 + aoff);
            }
#pragma unroll
            for (int pr = 0; pr < 2; ++pr) {
                unsigned boff = (unsigned)(((brow + pr * 16) * ROWSTR + bkk + koff) * 2);
                ldsm4(bh[pr], pb + 2 * PSTR * 2 + boff);
                ldsm4(bl[pr], pb + 3 * PSTR * 2 + boff);
            }
#pragma unroll
            for (int mf = 0; mf < 4; ++mf)
#pragma unroll
                for (int nf = 0; nf < 4; ++nf) {
                    unsigned* bhp = &bh[nf >> 1][(nf & 1) * 2];
                    unsigned* blp = &bl[nf >> 1][(nf & 1) * 2];
                    MMA16816(acc[mf][nf], ah[mf], bhp);
                    MMA16816(acc[mf][nf], ah[mf], blp);
                    MMA16816(acc[mf][nf], al[mf], bhp);
                }
        }
        if (t + 1 < NT) {
            __half* dst = smem + (buf ^ 1) * 4 * PSTR;
#pragma unroll
            for (int i = 0; i < 4; ++i) {
                unsigned h0, l0, h1, l1;
                cvt2(ra[i].x, ra[i].y, h0, l0); cvt2(ra[i].z, ra[i].w, h1, l1);
                *(uint2*)(dst + 0 * PSTR + soff[i]) = make_uint2(h0, h1);
                *(uint2*)(dst + 1 * PSTR + soff[i]) = make_uint2(l0, l1);
                cvt2(rb[i].x, rb[i].y, h0, l0); cvt2(rb[i].z, rb[i].w, h1, l1);
                *(uint2*)(dst + 2 * PSTR + soff[i]) = make_uint2(h0, h1);
                *(uint2*)(dst + 3 * PSTR + soff[i]) = make_uint2(l0, l1);
            }
        }
        __syncthreads();
        buf ^= 1;
    }

    // epilogue: accumulate split-K partials straight into d_out
    const int mb = m0 + wm * 64 + (lane >> 2);
    const int cb = n0 + wn * 32 + (lane & 3) * 2;
#pragma unroll
    for (int mf = 0; mf < 4; ++mf)
#pragma unroll
        for (int nf = 0; nf < 4; ++nf)
#pragma unroll
            for (int h = 0; h < 2; ++h) {
                int m = mb + mf * 16 + h * 8;
                int col = cb + nf * 8;
                atomicAdd(&out[(size_t)m * HDIM + col],     acc[mf][nf][h * 2]);
                atomicAdd(&out[(size_t)m * HDIM + col + 1], acc[mf][nf][h * 2 + 1]);
            }
}

// =====================================================================
extern "C" void kernel_launch(void* const* d_in, const int* in_sizes, int n_in,
                              void* d_out, int out_size)
{
    (void)in_sizes; (void)n_in; (void)out_size;
    const float* hidden = (const float*)d_in[0];
    const float* Wqkv   = (const float*)d_in[1];
    const float* bqkv   = (const float*)d_in[2];
    const float* Wgate  = (const float*)d_in[3];
    const float* Walpha = (const float*)d_in[4];
    const float* Wbeta  = (const float*)d_in[5];
    const float* Wout   = (const float*)d_in[6];
    const float* ssa    = (const float*)d_in[7];
    const float* dtb    = (const float*)d_in[8];
    const float* normw  = (const float*)d_in[9];
    const float* convk  = (const float*)d_in[10];
    const float* sstate = (const float*)d_in[11];
    const float* convst = (const float*)d_in[12];
    float* out = (float*)d_out;

    cudaFuncSetAttribute(k_gemm1, cudaFuncAttributeMaxDynamicSharedMemorySize, SMEM_BYTES);
    cudaFuncSetAttribute(k_gemm2, cudaFuncAttributeMaxDynamicSharedMemorySize, SMEM_BYTES);

    k_gemm1<<<dim3(65, 2), 256, SMEM_BYTES>>>(hidden, Wqkv, Wgate, Walpha, Wbeta);
    k_fuse <<<NB, 256>>>(bqkv, convk, convst, ssa, dtb, normw, sstate, out);
    k_gemm2<<<dim3(16, 2, 4), 256, SMEM_BYTES>>>(Wout, out);
}

// round 13
// speedup vs baseline: 1.0919x; 1.0809x over previous
#include <cuda_runtime.h>
#include <cuda_fp16.h>
#include <math.h>

#define NB   256
#define HDIM 2048
#define QKVD 8192
#define QSZ  4096
#define TGT  4096
#define NC   32

// ---------------- scratch (no allocations allowed) ----------------
__device__ float g_core_base[NB * TGT];     // raw qkv-tail gemm output
__device__ float g_gate[NB * TGT];          // sigmoid(hidden @ Wgate^T)
__device__ float g_ab[NB * 64];             // [a(32) | b(32)] per batch
__device__ float g_core[NB * TGT];          // normalized gated core

__device__ __forceinline__ float sigmoidf_(float x) { return 1.0f / (1.0f + expf(-x)); }

// ---------------- mma.sync fp16 plumbing ----------------
__device__ __forceinline__ void ldsm4(unsigned* r, unsigned addr) {
    asm volatile("ldmatrix.sync.aligned.m8n8.x4.shared.b16 {%0,%1,%2,%3}, [%4];"
                 : "=r"(r[0]), "=r"(r[1]), "=r"(r[2]), "=r"(r[3]) : "r"(addr));
}
#define MMA16816(d, a, b) asm volatile( \
    "mma.sync.aligned.m16n8k16.row.col.f32.f16.f16.f32 " \
    "{%0,%1,%2,%3}, {%4,%5,%6,%7}, {%8,%9}, {%0,%1,%2,%3};" \
    : "+f"((d)[0]), "+f"((d)[1]), "+f"((d)[2]), "+f"((d)[3]) \
    : "r"((a)[0]), "r"((a)[1]), "r"((a)[2]), "r"((a)[3]), "r"((b)[0]), "r"((b)[1]))

// split x into fp16 hi + fp16 lo (pairs packed into u32, low element first)
__device__ __forceinline__ void cvt2(float a, float b, unsigned& hi, unsigned& lo) {
    __half2 h = __floats2half2_rn(a, b);
    float ra = a - __low2float(h);
    float rb = b - __high2float(h);
    __half2 l = __floats2half2_rn(ra, rb);
    hi = *(unsigned*)&h;
    lo = *(unsigned*)&l;
}

// smem geometry: BM=64, BN=128, BK=32. Row stride padded 32->40 (no LDSM conflicts)
// planes (in halves): Ahi[64*40] Alo[64*40] Bhi[128*40] Blo[128*40], double buffered
#define ROWSTR 40
#define APL    (64 * ROWSTR)     // 2560 halves
#define BPL    (128 * ROWSTR)    // 5120 halves
#define BUFH   (2 * APL + 2 * BPL)  // 15360 halves per buffer
#define OFF_AH 0
#define OFF_AL APL
#define OFF_BH (2 * APL)
#define OFF_BL (2 * APL + BPL)
#define SMEM_BYTES (2 * BUFH * 2)   // 61440 bytes

// =====================================================================
// K1: fused GEMM over N = [qkv tail | gate | alpha/beta], M=256, K=2048.
// BM=64, BN=128, BK=32, 8 warps (2x4), warp tile 32x32, fp16 hi/lo mma.
// Gate blocks (kind==1) use 2-pass (drop A_lo*B_hi); others 3-pass.
// __launch_bounds__(256,2): 2 CTAs/SM so producer phases of one CTA
// overlap the MMA phase of the other (tensor-pipe fill).
// =====================================================================
__global__ void __launch_bounds__(256, 2) k_gemm1(
    const float* __restrict__ A,       // hidden [256,2048]
    const float* __restrict__ Wqkv,    // [8192,2048]
    const float* __restrict__ Wgate,   // [4096,2048]
    const float* __restrict__ Walpha,  // [32,2048]
    const float* __restrict__ Wbeta)   // [32,2048]
{
    extern __shared__ __half smem[];
    const int tid  = threadIdx.x;
    const int m0   = blockIdx.y * 64;
    const int nblk = blockIdx.x;
    const int kind = (nblk < 32) ? 0 : (nblk < 64 ? 1 : 2);
    const bool three = (kind != 1);

    // per-thread load slots: A 2x float4 (64x32), B 4x float4 (128x32)
    const float* pA[2]; int soffA[2];
    const float* pB[4]; int soffB[4];
#pragma unroll
    for (int i = 0; i < 2; ++i) {
        int c = tid + i * 256;
        int r = c >> 3, kc = c & 7;
        soffA[i] = r * ROWSTR + kc * 4;
        pA[i] = A + (size_t)(m0 + r) * HDIM + kc * 4;
    }
#pragma unroll
    for (int i = 0; i < 4; ++i) {
        int c = tid + i * 256;
        int r = c >> 3, kc = c & 7;
        soffB[i] = r * ROWSTR + kc * 4;
        const float* rp;
        if (kind == 0)      rp = Wqkv  + (size_t)(QSZ + nblk * 128 + r) * HDIM;
        else if (kind == 1) rp = Wgate + (size_t)((nblk - 32) * 128 + r) * HDIM;
        else rp = (r < 32) ? Walpha + (size_t)r * HDIM
                 : (r < 64) ? Wbeta + (size_t)(r - 32) * HDIM
                            : Walpha + (size_t)(r & 31) * HDIM;   // dummy rows
        pB[i] = rp + kc * 4;
    }

    const unsigned sbase = (unsigned)__cvta_generic_to_shared(smem);
    const int lane = tid & 31, wid = tid >> 5;
    const int wm = wid >> 2, wn = wid & 3;   // 2 x 4 warps

    float acc[2][4][4];
#pragma unroll
    for (int x = 0; x < 2; ++x)
#pragma unroll
        for (int y = 0; y < 4; ++y)
#pragma unroll
            for (int z = 0; z < 4; ++z) acc[x][y][z] = 0.f;

    const int arow = wm * 32 + (lane & 15);
    const int akk  = (lane >> 4) << 3;
    const int brow = wn * 32 + ((lane >> 4) << 3) + (lane & 7);
    const int bkk  = ((lane >> 3) & 1) << 3;

    float4 ra[2], rb[4];
#pragma unroll
    for (int i = 0; i < 2; ++i) ra[i] = *(const float4*)pA[i];
#pragma unroll
    for (int i = 0; i < 4; ++i) rb[i] = *(const float4*)pB[i];
    {
        __half* dst = smem;
#pragma unroll
        for (int i = 0; i < 2; ++i) {
            unsigned h0, l0, h1, l1;
            cvt2(ra[i].x, ra[i].y, h0, l0); cvt2(ra[i].z, ra[i].w, h1, l1);
            *(uint2*)(dst + OFF_AH + soffA[i]) = make_uint2(h0, h1);
            *(uint2*)(dst + OFF_AL + soffA[i]) = make_uint2(l0, l1);
        }
#pragma unroll
        for (int i = 0; i < 4; ++i) {
            unsigned h0, l0, h1, l1;
            cvt2(rb[i].x, rb[i].y, h0, l0); cvt2(rb[i].z, rb[i].w, h1, l1);
            *(uint2*)(dst + OFF_BH + soffB[i]) = make_uint2(h0, h1);
            *(uint2*)(dst + OFF_BL + soffB[i]) = make_uint2(l0, l1);
        }
    }
    __syncthreads();

    const int NT = HDIM / 32;
    int buf = 0;
    for (int t = 0; t < NT; ++t) {
        if (t + 1 < NT) {
#pragma unroll
            for (int i = 0; i < 2; ++i) ra[i] = *(const float4*)(pA[i] + (t + 1) * 32);
#pragma unroll
            for (int i = 0; i < 4; ++i) rb[i] = *(const float4*)(pB[i] + (t + 1) * 32);
        }
        const unsigned pb = sbase + (unsigned)(buf * BUFH * 2);
#pragma unroll
        for (int ks = 0; ks < 2; ++ks) {
            const int koff = ks * 16;
            unsigned ah[2][4], al[2][4], bh[2][4], bl[2][4];
#pragma unroll
            for (int mf = 0; mf < 2; ++mf) {
                unsigned aoff = (unsigned)(((arow + mf * 16) * ROWSTR + akk + koff) * 2);
                ldsm4(ah[mf], pb + OFF_AH * 2 + aoff);
                if (three) ldsm4(al[mf], pb + OFF_AL * 2 + aoff);
            }
#pragma unroll
            for (int pr = 0; pr < 2; ++pr) {
                unsigned boff = (unsigned)(((brow + pr * 16) * ROWSTR + bkk + koff) * 2);
                ldsm4(bh[pr], pb + OFF_BH * 2 + boff);
                ldsm4(bl[pr], pb + OFF_BL * 2 + boff);
            }
#pragma unroll
            for (int mf = 0; mf < 2; ++mf)
#pragma unroll
                for (int nf = 0; nf < 4; ++nf) {
                    unsigned* bhp = &bh[nf >> 1][(nf & 1) * 2];
                    unsigned* blp = &bl[nf >> 1][(nf & 1) * 2];
                    MMA16816(acc[mf][nf], ah[mf], bhp);
                    MMA16816(acc[mf][nf], ah[mf], blp);
                    if (three) MMA16816(acc[mf][nf], al[mf], bhp);
                }
        }
        if (t + 1 < NT) {
            __half* dst = smem + (buf ^ 1) * BUFH;
#pragma unroll
            for (int i = 0; i < 2; ++i) {
                unsigned h0, l0, h1, l1;
                cvt2(ra[i].x, ra[i].y, h0, l0); cvt2(ra[i].z, ra[i].w, h1, l1);
                *(uint2*)(dst + OFF_AH + soffA[i]) = make_uint2(h0, h1);
                *(uint2*)(dst + OFF_AL + soffA[i]) = make_uint2(l0, l1);
            }
#pragma unroll
            for (int i = 0; i < 4; ++i) {
                unsigned h0, l0, h1, l1;
                cvt2(rb[i].x, rb[i].y, h0, l0); cvt2(rb[i].z, rb[i].w, h1, l1);
                *(uint2*)(dst + OFF_BH + soffB[i]) = make_uint2(h0, h1);
                *(uint2*)(dst + OFF_BL + soffB[i]) = make_uint2(l0, l1);
            }
        }
        __syncthreads();
        buf ^= 1;
    }

    // epilogue
    const int mb = m0 + wm * 32 + (lane >> 2);
    const int cb = wn * 32 + (lane & 3) * 2;
#pragma unroll
    for (int mf = 0; mf < 2; ++mf)
#pragma unroll
        for (int nf = 0; nf < 4; ++nf)
#pragma unroll
            for (int h = 0; h < 2; ++h) {
                int m = mb + mf * 16 + h * 8;
                int col = cb + nf * 8;
                float v0 = acc[mf][nf][h * 2], v1 = acc[mf][nf][h * 2 + 1];
                if (kind == 0) {
                    *(float2*)&g_core_base[(size_t)m * TGT + nblk * 128 + col] = make_float2(v0, v1);
                } else if (kind == 1) {
                    *(float2*)&g_gate[(size_t)m * TGT + (nblk - 32) * 128 + col] =
                        make_float2(sigmoidf_(v0), sigmoidf_(v1));
                } else if (col < 64) {
                    *(float2*)&g_ab[(size_t)m * 64 + col] = make_float2(v0, v1);
                }
            }
}

// =====================================================================
// K2: per-batch fused conv + SSM + RMS + gate; also zeroes d_out so the
// out-GEMM can accumulate with atomics. 1 CTA per batch row.
// =====================================================================
__global__ void __launch_bounds__(256) k_fuse(
    const float* __restrict__ bqkv,
    const float* __restrict__ convk,    // [8192,4]
    const float* __restrict__ convst,   // [256,4,8192]
    const float* __restrict__ ssa,
    const float* __restrict__ dtb,
    const float* __restrict__ normw,
    const float* __restrict__ sstate,
    float* __restrict__ out)            // [256,2048] -> zeroed here
{
    __shared__ float s_conv[TGT];
    __shared__ float kg[NC], vg[NC], ssig[NC], red[8];
    __shared__ float s_scale, s_wmean;
    const int b = blockIdx.x, tid = threadIdx.x;
    const int lane = tid & 31, w = tid >> 5;

#pragma unroll
    for (int i = 0; i < 8; ++i) out[(size_t)b * HDIM + tid + i * 256] = 0.f;

#pragma unroll
    for (int i = 0; i < 16; ++i) {
        int idx = tid + i * 256;
        int d = QSZ + idx;
        float val = g_core_base[(size_t)b * TGT + idx] + bqkv[d];
        float4 ck = *(const float4*)(convk + (size_t)d * 4);
        float co = val * ck.w
                 + convst[((size_t)b * 4 + 1) * QKVD + d] * ck.x
                 + convst[((size_t)b * 4 + 2) * QKVD + d] * ck.y
                 + convst[((size_t)b * 4 + 3) * QKVD + d] * ck.z;
        s_conv[idx] = co;
    }
    if (tid == 0) {
        float wm = 0.f;
        for (int i = 0; i < 128; ++i) wm += normw[i];
        s_wmean = wm * (1.0f / 128.0f);
    }
    __syncthreads();

    {   // 64 group means of 64 elements, 4 threads per group
        int gg = tid >> 2, sub = tid & 3;
        const float* p = s_conv + gg * 64 + sub * 16;
        float s = 0.f;
#pragma unroll
        for (int i = 0; i < 16; ++i) s += p[i];
        s += __shfl_xor_sync(0xFFFFFFFFu, s, 1);
        s += __shfl_xor_sync(0xFFFFFFFFu, s, 2);
        if (sub == 0) {
            float mn = s * (1.0f / 64.0f);
            if (gg < NC) kg[gg] = mn; else vg[gg - NC] = mn;
        }
    }
    __syncthreads();

    if (tid < NC) {
        int c = tid;
        float av = g_ab[(size_t)b * 64 + c];
        float bv = g_ab[(size_t)b * 64 + 32 + c];
        float x  = av + dtb[c];
        float sp = (x > 20.f) ? x : log1pf(expf(x));
        float g  = -expf(ssa[c]) * sp;
        float ns = expf(g) * sstate[(size_t)b * NC + c] + sigmoidf_(bv) * vg[c];
        ssig[c]  = ns * sigmoidf_(kg[c]);
    }
    __syncthreads();

    float cv[16]; float sq = 0.f;
#pragma unroll
    for (int i = 0; i < 16; ++i) {
        int idx = tid + i * 256;
        float v = s_conv[idx] + ssig[idx >> 7];
        cv[i] = v; sq += v * v;
    }
#pragma unroll
    for (int o = 16; o; o >>= 1) sq += __shfl_xor_sync(0xFFFFFFFFu, sq, o);
    if (lane == 0) red[w] = sq;
    __syncthreads();
    if (tid == 0) {
        float t = 0.f;
        for (int i = 0; i < 8; ++i) t += red[i];
        s_scale = rsqrtf(t * (1.0f / (float)TGT) + 1e-6f);
    }
    __syncthreads();

    const float scl = s_scale * s_wmean;
#pragma unroll
    for (int i = 0; i < 16; ++i) {
        int idx = tid + i * 256;
        g_core[(size_t)b * TGT + idx] = cv[i] * scl * g_gate[(size_t)b * TGT + idx];
    }
}

// =====================================================================
// K3: out GEMM [256,2048] = g_core[256,4096] @ Wout[2048,4096]^T,
// BM=64, split-K=4 (blockIdx.z), fp16 hi/lo 3-pass, atomicAdd -> d_out.
// =====================================================================
__global__ void __launch_bounds__(256, 2) k_gemm2(const float* __restrict__ Wout,
                                                  float* __restrict__ out)
{
    extern __shared__ __half smem[];
    const int tid = threadIdx.x;
    const int m0  = blockIdx.y * 64;
    const int n0  = blockIdx.x * 128;
    const int s   = blockIdx.z;
    const int kbeg = s * 1024;

    const float* pA[2]; int soffA[2];
    const float* pB[4]; int soffB[4];
#pragma unroll
    for (int i = 0; i < 2; ++i) {
        int c = tid + i * 256;
        int r = c >> 3, kc = c & 7;
        soffA[i] = r * ROWSTR + kc * 4;
        pA[i] = g_core + (size_t)(m0 + r) * TGT + kbeg + kc * 4;
    }
#pragma unroll
    for (int i = 0; i < 4; ++i) {
        int c = tid + i * 256;
        int r = c >> 3, kc = c & 7;
        soffB[i] = r * ROWSTR + kc * 4;
        pB[i] = Wout + (size_t)(n0 + r) * TGT + kbeg + kc * 4;
    }

    const unsigned sbase = (unsigned)__cvta_generic_to_shared(smem);
    const int lane = tid & 31, wid = tid >> 5;
    const int wm = wid >> 2, wn = wid & 3;

    float acc[2][4][4];
#pragma unroll
    for (int x = 0; x < 2; ++x)
#pragma unroll
        for (int y = 0; y < 4; ++y)
#pragma unroll
            for (int z = 0; z < 4; ++z) acc[x][y][z] = 0.f;

    const int arow = wm * 32 + (lane & 15);
    const int akk  = (lane >> 4) << 3;
    const int brow = wn * 32 + ((lane >> 4) << 3) + (lane & 7);
    const int bkk  = ((lane >> 3) & 1) << 3;

    float4 ra[2], rb[4];
#pragma unroll
    for (int i = 0; i < 2; ++i) ra[i] = *(const float4*)pA[i];
#pragma unroll
    for (int i = 0; i < 4; ++i) rb[i] = *(const float4*)pB[i];
    {
        __half* dst = smem;
#pragma unroll
        for (int i = 0; i < 2; ++i) {
            unsigned h0, l0, h1, l1;
            cvt2(ra[i].x, ra[i].y, h0, l0); cvt2(ra[i].z, ra[i].w, h1, l1);
            *(uint2*)(dst + OFF_AH + soffA[i]) = make_uint2(h0, h1);
            *(uint2*)(dst + OFF_AL + soffA[i]) = make_uint2(l0, l1);
        }
#pragma unroll
        for (int i = 0; i < 4; ++i) {
            unsigned h0, l0, h1, l1;
            cvt2(rb[i].x, rb[i].y, h0, l0); cvt2(rb[i].z, rb[i].w, h1, l1);
            *(uint2*)(dst + OFF_BH + soffB[i]) = make_uint2(h0, h1);
            *(uint2*)(dst + OFF_BL + soffB[i]) = make_uint2(l0, l1);
        }
    }
    __syncthreads();

    const int NT = 1024 / 32;
    int buf = 0;
    for (int t = 0; t < NT; ++t) {
        if (t + 1 < NT) {
#pragma unroll
            for (int i = 0; i < 2; ++i) ra[i] = *(const float4*)(pA[i] + (t + 1) * 32);
#pragma unroll
            for (int i = 0; i < 4; ++i) rb[i] = *(const float4*)(pB[i] + (t + 1) * 32);
        }
        const unsigned pb = sbase + (unsigned)(buf * BUFH * 2);
#pragma unroll
        for (int ks = 0; ks < 2; ++ks) {
            const int koff = ks * 16;
            unsigned ah[2][4], al[2][4], bh[2][4], bl[2][4];
#pragma unroll
            for (int mf = 0; mf < 2; ++mf) {
                unsigned aoff = (unsigned)(((arow + mf * 16) * ROWSTR + akk + koff) * 2);
                ldsm4(ah[mf], pb + OFF_AH * 2 + aoff);
                ldsm4(al[mf], pb + OFF_AL * 2 + aoff);
            }
#pragma unroll
            for (int pr = 0; pr < 2; ++pr) {
                unsigned boff = (unsigned)(((brow + pr * 16) * ROWSTR + bkk + koff) * 2);
                ldsm4(bh[pr], pb + OFF_BH * 2 + boff);
                ldsm4(bl[pr], pb + OFF_BL * 2 + boff);
            }
#pragma unroll
            for (int mf = 0; mf < 2; ++mf)
#pragma unroll
                for (int nf = 0; nf < 4; ++nf) {
                    unsigned* bhp = &bh[nf >> 1][(nf & 1) * 2];
                    unsigned* blp = &bl[nf >> 1][(nf & 1) * 2];
                    MMA16816(acc[mf][nf], ah[mf], bhp);
                    MMA16816(acc[mf][nf], ah[mf], blp);
                    MMA16816(acc[mf][nf], al[mf], bhp);
                }
        }
        if (t + 1 < NT) {
            __half* dst = smem + (buf ^ 1) * BUFH;
#pragma unroll
            for (int i = 0; i < 2; ++i) {
                unsigned h0, l0, h1, l1;
                cvt2(ra[i].x, ra[i].y, h0, l0); cvt2(ra[i].z, ra[i].w, h1, l1);
                *(uint2*)(dst + OFF_AH + soffA[i]) = make_uint2(h0, h1);
                *(uint2*)(dst + OFF_AL + soffA[i]) = make_uint2(l0, l1);
            }
#pragma unroll
            for (int i = 0; i < 4; ++i) {
                unsigned h0, l0, h1, l1;
                cvt2(rb[i].x, rb[i].y, h0, l0); cvt2(rb[i].z, rb[i].w, h1, l1);
                *(uint2*)(dst + OFF_BH + soffB[i]) = make_uint2(h0, h1);
                *(uint2*)(dst + OFF_BL + soffB[i]) = make_uint2(l0, l1);
            }
        }
        __syncthreads();
        buf ^= 1;
    }

    // epilogue: accumulate split-K partials straight into d_out
    const int mb = m0 + wm * 32 + (lane >> 2);
    const int cb = n0 + wn * 32 + (lane & 3) * 2;
#pragma unroll
    for (int mf = 0; mf < 2; ++mf)
#pragma unroll
        for (int nf = 0; nf < 4; ++nf)
#pragma unroll
            for (int h = 0; h < 2; ++h) {
                int m = mb + mf * 16 + h * 8;
                int col = cb + nf * 8;
                atomicAdd(&out[(size_t)m * HDIM + col],     acc[mf][nf][h * 2]);
                atomicAdd(&out[(size_t)m * HDIM + col + 1], acc[mf][nf][h * 2 + 1]);
            }
}

// =====================================================================
extern "C" void kernel_launch(void* const* d_in, const int* in_sizes, int n_in,
                              void* d_out, int out_size)
{
    (void)in_sizes; (void)n_in; (void)out_size;
    const float* hidden = (const float*)d_in[0];
    const float* Wqkv   = (const float*)d_in[1];
    const float* bqkv   = (const float*)d_in[2];
    const float* Wgate  = (const float*)d_in[3];
    const float* Walpha = (const float*)d_in[4];
    const float* Wbeta  = (const float*)d_in[5];
    const float* Wout   = (const float*)d_in[6];
    const float* ssa    = (const float*)d_in[7];
    const float* dtb    = (const float*)d_in[8];
    const float* normw  = (const float*)d_in[9];
    const float* convk  = (const float*)d_in[10];
    const float* sstate = (const float*)d_in[11];
    const float* convst = (const float*)d_in[12];
    float* out = (float*)d_out;

    cudaFuncSetAttribute(k_gemm1, cudaFuncAttributeMaxDynamicSharedMemorySize, SMEM_BYTES);
    cudaFuncSetAttribute(k_gemm2, cudaFuncAttributeMaxDynamicSharedMemorySize, SMEM_BYTES);

    k_gemm1<<<dim3(65, 4), 256, SMEM_BYTES>>>(hidden, Wqkv, Wgate, Walpha, Wbeta);
    k_fuse <<<NB, 256>>>(bqkv, convk, convst, ssa, dtb, normw, sstate, out);
    k_gemm2<<<dim3(16, 4, 4), 256, SMEM_BYTES>>>(Wout, out);
}

// round 14
// speedup vs baseline: 1.1721x; 1.0734x over previous
#include <cuda_runtime.h>
#include <cuda_fp16.h>
#include <math.h>

#define NB   256
#define HDIM 2048
#define QKVD 8192
#define QSZ  4096
#define TGT  4096
#define NC   32

// ---------------- scratch (no allocations allowed) ----------------
__device__ float g_core_base[NB * TGT];     // raw qkv-tail gemm output
__device__ float g_gate[NB * TGT];          // sigmoid(hidden @ Wgate^T)
__device__ float g_ab[NB * 64];             // [a(32) | b(32)] per batch
__device__ float g_core[NB * TGT];          // normalized gated core

__device__ __forceinline__ float sigmoidf_(float x) { return 1.0f / (1.0f + expf(-x)); }

// ---------------- mma.sync fp16 plumbing ----------------
__device__ __forceinline__ void ldsm4(unsigned* r, unsigned addr) {
    asm volatile("ldmatrix.sync.aligned.m8n8.x4.shared.b16 {%0,%1,%2,%3}, [%4];"
                 : "=r"(r[0]), "=r"(r[1]), "=r"(r[2]), "=r"(r[3]) : "r"(addr));
}
#define MMA16816(d, a, b) asm volatile( \
    "mma.sync.aligned.m16n8k16.row.col.f32.f16.f16.f32 " \
    "{%0,%1,%2,%3}, {%4,%5,%6,%7}, {%8,%9}, {%0,%1,%2,%3};" \
    : "+f"((d)[0]), "+f"((d)[1]), "+f"((d)[2]), "+f"((d)[3]) \
    : "r"((a)[0]), "r"((a)[1]), "r"((a)[2]), "r"((a)[3]), "r"((b)[0]), "r"((b)[1]))

// split x into fp16 hi + fp16 lo (pairs packed into u32, low element first)
__device__ __forceinline__ void cvt2(float a, float b, unsigned& hi, unsigned& lo) {
    __half2 h = __floats2half2_rn(a, b);
    float ra = a - __low2float(h);
    float rb = b - __high2float(h);
    __half2 l = __floats2half2_rn(ra, rb);
    hi = *(unsigned*)&h;
    lo = *(unsigned*)&l;
}
__device__ __forceinline__ unsigned cvt2hi(float a, float b) {
    __half2 h = __floats2half2_rn(a, b);
    return *(unsigned*)&h;
}

// smem geometry: BM=64, BN=128, BK=32. Row stride padded 32->40 (no LDSM conflicts)
// planes (in halves): Ahi[64*40] Alo[64*40] Bhi[128*40] Blo[128*40], double buffered
// (Alo plane only written/read on 3-pass blocks)
#define ROWSTR 40
#define APL    (64 * ROWSTR)     // 2560 halves
#define BPL    (128 * ROWSTR)    // 5120 halves
#define BUFH   (2 * APL + 2 * BPL)  // 15360 halves per buffer
#define OFF_AH 0
#define OFF_AL APL
#define OFF_BH (2 * APL)
#define OFF_BL (2 * APL + BPL)
#define SMEM_BYTES (2 * BUFH * 2)   // 61440 bytes

// =====================================================================
// K1: fused GEMM over N = [qkv tail | gate | alpha/beta], M=256, K=2048.
// BM=64, BN=128, BK=32, 8 warps (2x4), warp tile 32x32, fp16 hi/lo mma.
// 2-pass (A_hi*B_hi + A_hi*B_lo) for qkv/gate blocks; 3-pass only for the
// alpha/beta block (exp-sensitive path). 2 CTAs/SM.
// =====================================================================
__global__ void __launch_bounds__(256, 2) k_gemm1(
    const float* __restrict__ A,       // hidden [256,2048]
    const float* __restrict__ Wqkv,    // [8192,2048]
    const float* __restrict__ Wgate,   // [4096,2048]
    const float* __restrict__ Walpha,  // [32,2048]
    const float* __restrict__ Wbeta)   // [32,2048]
{
    extern __shared__ __half smem[];
    const int tid  = threadIdx.x;
    const int m0   = blockIdx.y * 64;
    const int nblk = blockIdx.x;
    const int kind = (nblk < 32) ? 0 : (nblk < 64 ? 1 : 2);
    const bool three = (kind == 2);    // 3rd pass only for alpha/beta block

    // per-thread load slots: A 2x float4 (64x32), B 4x float4 (128x32)
    const float* pA[2]; int soffA[2];
    const float* pB[4]; int soffB[4];
#pragma unroll
    for (int i = 0; i < 2; ++i) {
        int c = tid + i * 256;
        int r = c >> 3, kc = c & 7;
        soffA[i] = r * ROWSTR + kc * 4;
        pA[i] = A + (size_t)(m0 + r) * HDIM + kc * 4;
    }
#pragma unroll
    for (int i = 0; i < 4; ++i) {
        int c = tid + i * 256;
        int r = c >> 3, kc = c & 7;
        soffB[i] = r * ROWSTR + kc * 4;
        const float* rp;
        if (kind == 0)      rp = Wqkv  + (size_t)(QSZ + nblk * 128 + r) * HDIM;
        else if (kind == 1) rp = Wgate + (size_t)((nblk - 32) * 128 + r) * HDIM;
        else rp = (r < 32) ? Walpha + (size_t)r * HDIM
                 : (r < 64) ? Wbeta + (size_t)(r - 32) * HDIM
                            : Walpha + (size_t)(r & 31) * HDIM;   // dummy rows
        pB[i] = rp + kc * 4;
    }

    const unsigned sbase = (unsigned)__cvta_generic_to_shared(smem);
    const int lane = tid & 31, wid = tid >> 5;
    const int wm = wid >> 2, wn = wid & 3;   // 2 x 4 warps

    float acc[2][4][4];
#pragma unroll
    for (int x = 0; x < 2; ++x)
#pragma unroll
        for (int y = 0; y < 4; ++y)
#pragma unroll
            for (int z = 0; z < 4; ++z) acc[x][y][z] = 0.f;

    const int arow = wm * 32 + (lane & 15);
    const int akk  = (lane >> 4) << 3;
    const int brow = wn * 32 + ((lane >> 4) << 3) + (lane & 7);
    const int bkk  = ((lane >> 3) & 1) << 3;

    float4 ra[2], rb[4];
#pragma unroll
    for (int i = 0; i < 2; ++i) ra[i] = *(const float4*)pA[i];
#pragma unroll
    for (int i = 0; i < 4; ++i) rb[i] = *(const float4*)pB[i];
    {
        __half* dst = smem;
#pragma unroll
        for (int i = 0; i < 2; ++i) {
            unsigned h0, l0, h1, l1;
            cvt2(ra[i].x, ra[i].y, h0, l0); cvt2(ra[i].z, ra[i].w, h1, l1);
            *(uint2*)(dst + OFF_AH + soffA[i]) = make_uint2(h0, h1);
            if (three) *(uint2*)(dst + OFF_AL + soffA[i]) = make_uint2(l0, l1);
        }
#pragma unroll
        for (int i = 0; i < 4; ++i) {
            unsigned h0, l0, h1, l1;
            cvt2(rb[i].x, rb[i].y, h0, l0); cvt2(rb[i].z, rb[i].w, h1, l1);
            *(uint2*)(dst + OFF_BH + soffB[i]) = make_uint2(h0, h1);
            *(uint2*)(dst + OFF_BL + soffB[i]) = make_uint2(l0, l1);
        }
    }
    __syncthreads();

    const int NT = HDIM / 32;
    int buf = 0;
    for (int t = 0; t < NT; ++t) {
        if (t + 1 < NT) {
#pragma unroll
            for (int i = 0; i < 2; ++i) ra[i] = *(const float4*)(pA[i] + (t + 1) * 32);
#pragma unroll
            for (int i = 0; i < 4; ++i) rb[i] = *(const float4*)(pB[i] + (t + 1) * 32);
        }
        const unsigned pb = sbase + (unsigned)(buf * BUFH * 2);
#pragma unroll
        for (int ks = 0; ks < 2; ++ks) {
            const int koff = ks * 16;
            unsigned ah[2][4], al[2][4], bh[2][4], bl[2][4];
#pragma unroll
            for (int mf = 0; mf < 2; ++mf) {
                unsigned aoff = (unsigned)(((arow + mf * 16) * ROWSTR + akk + koff) * 2);
                ldsm4(ah[mf], pb + OFF_AH * 2 + aoff);
                if (three) ldsm4(al[mf], pb + OFF_AL * 2 + aoff);
            }
#pragma unroll
            for (int pr = 0; pr < 2; ++pr) {
                unsigned boff = (unsigned)(((brow + pr * 16) * ROWSTR + bkk + koff) * 2);
                ldsm4(bh[pr], pb + OFF_BH * 2 + boff);
                ldsm4(bl[pr], pb + OFF_BL * 2 + boff);
            }
#pragma unroll
            for (int mf = 0; mf < 2; ++mf)
#pragma unroll
                for (int nf = 0; nf < 4; ++nf) {
                    unsigned* bhp = &bh[nf >> 1][(nf & 1) * 2];
                    unsigned* blp = &bl[nf >> 1][(nf & 1) * 2];
                    MMA16816(acc[mf][nf], ah[mf], bhp);
                    MMA16816(acc[mf][nf], ah[mf], blp);
                    if (three) MMA16816(acc[mf][nf], al[mf], bhp);
                }
        }
        if (t + 1 < NT) {
            __half* dst = smem + (buf ^ 1) * BUFH;
#pragma unroll
            for (int i = 0; i < 2; ++i) {
                unsigned h0, l0, h1, l1;
                cvt2(ra[i].x, ra[i].y, h0, l0); cvt2(ra[i].z, ra[i].w, h1, l1);
                *(uint2*)(dst + OFF_AH + soffA[i]) = make_uint2(h0, h1);
                if (three) *(uint2*)(dst + OFF_AL + soffA[i]) = make_uint2(l0, l1);
            }
#pragma unroll
            for (int i = 0; i < 4; ++i) {
                unsigned h0, l0, h1, l1;
                cvt2(rb[i].x, rb[i].y, h0, l0); cvt2(rb[i].z, rb[i].w, h1, l1);
                *(uint2*)(dst + OFF_BH + soffB[i]) = make_uint2(h0, h1);
                *(uint2*)(dst + OFF_BL + soffB[i]) = make_uint2(l0, l1);
            }
        }
        __syncthreads();
        buf ^= 1;
    }

    // epilogue
    const int mb = m0 + wm * 32 + (lane >> 2);
    const int cb = wn * 32 + (lane & 3) * 2;
#pragma unroll
    for (int mf = 0; mf < 2; ++mf)
#pragma unroll
        for (int nf = 0; nf < 4; ++nf)
#pragma unroll
            for (int h = 0; h < 2; ++h) {
                int m = mb + mf * 16 + h * 8;
                int col = cb + nf * 8;
                float v0 = acc[mf][nf][h * 2], v1 = acc[mf][nf][h * 2 + 1];
                if (kind == 0) {
                    *(float2*)&g_core_base[(size_t)m * TGT + nblk * 128 + col] = make_float2(v0, v1);
                } else if (kind == 1) {
                    *(float2*)&g_gate[(size_t)m * TGT + (nblk - 32) * 128 + col] =
                        make_float2(sigmoidf_(v0), sigmoidf_(v1));
                } else if (col < 64) {
                    *(float2*)&g_ab[(size_t)m * 64 + col] = make_float2(v0, v1);
                }
            }
}

// =====================================================================
// K2: per-batch fused conv + SSM + RMS + gate; also zeroes d_out so the
// out-GEMM can accumulate with atomics. 1 CTA per batch row.
// =====================================================================
__global__ void __launch_bounds__(256) k_fuse(
    const float* __restrict__ bqkv,
    const float* __restrict__ convk,    // [8192,4]
    const float* __restrict__ convst,   // [256,4,8192]
    const float* __restrict__ ssa,
    const float* __restrict__ dtb,
    const float* __restrict__ normw,
    const float* __restrict__ sstate,
    float* __restrict__ out)            // [256,2048] -> zeroed here
{
    __shared__ float s_conv[TGT];
    __shared__ float kg[NC], vg[NC], ssig[NC], red[8];
    __shared__ float s_scale, s_wmean;
    const int b = blockIdx.x, tid = threadIdx.x;
    const int lane = tid & 31, w = tid >> 5;

#pragma unroll
    for (int i = 0; i < 8; ++i) out[(size_t)b * HDIM + tid + i * 256] = 0.f;

#pragma unroll
    for (int i = 0; i < 16; ++i) {
        int idx = tid + i * 256;
        int d = QSZ + idx;
        float val = g_core_base[(size_t)b * TGT + idx] + bqkv[d];
        float4 ck = *(const float4*)(convk + (size_t)d * 4);
        float co = val * ck.w
                 + convst[((size_t)b * 4 + 1) * QKVD + d] * ck.x
                 + convst[((size_t)b * 4 + 2) * QKVD + d] * ck.y
                 + convst[((size_t)b * 4 + 3) * QKVD + d] * ck.z;
        s_conv[idx] = co;
    }
    if (tid == 0) {
        float wm = 0.f;
        for (int i = 0; i < 128; ++i) wm += normw[i];
        s_wmean = wm * (1.0f / 128.0f);
    }
    __syncthreads();

    {   // 64 group means of 64 elements, 4 threads per group
        int gg = tid >> 2, sub = tid & 3;
        const float* p = s_conv + gg * 64 + sub * 16;
        float s = 0.f;
#pragma unroll
        for (int i = 0; i < 16; ++i) s += p[i];
        s += __shfl_xor_sync(0xFFFFFFFFu, s, 1);
        s += __shfl_xor_sync(0xFFFFFFFFu, s, 2);
        if (sub == 0) {
            float mn = s * (1.0f / 64.0f);
            if (gg < NC) kg[gg] = mn; else vg[gg - NC] = mn;
        }
    }
    __syncthreads();

    if (tid < NC) {
        int c = tid;
        float av = g_ab[(size_t)b * 64 + c];
        float bv = g_ab[(size_t)b * 64 + 32 + c];
        float x  = av + dtb[c];
        float sp = (x > 20.f) ? x : log1pf(expf(x));
        float g  = -expf(ssa[c]) * sp;
        float ns = expf(g) * sstate[(size_t)b * NC + c] + sigmoidf_(bv) * vg[c];
        ssig[c]  = ns * sigmoidf_(kg[c]);
    }
    __syncthreads();

    float cv[16]; float sq = 0.f;
#pragma unroll
    for (int i = 0; i < 16; ++i) {
        int idx = tid + i * 256;
        float v = s_conv[idx] + ssig[idx >> 7];
        cv[i] = v; sq += v * v;
    }
#pragma unroll
    for (int o = 16; o; o >>= 1) sq += __shfl_xor_sync(0xFFFFFFFFu, sq, o);
    if (lane == 0) red[w] = sq;
    __syncthreads();
    if (tid == 0) {
        float t = 0.f;
        for (int i = 0; i < 8; ++i) t += red[i];
        s_scale = rsqrtf(t * (1.0f / (float)TGT) + 1e-6f);
    }
    __syncthreads();

    const float scl = s_scale * s_wmean;
#pragma unroll
    for (int i = 0; i < 16; ++i) {
        int idx = tid + i * 256;
        g_core[(size_t)b * TGT + idx] = cv[i] * scl * g_gate[(size_t)b * TGT + idx];
    }
}

// =====================================================================
// K3: out GEMM [256,2048] = g_core[256,4096] @ Wout[2048,4096]^T,
// BM=64, split-K=4, fp16 hi/lo 2-pass, atomicAdd -> d_out.
// =====================================================================
__global__ void __launch_bounds__(256, 2) k_gemm2(const float* __restrict__ Wout,
                                                  float* __restrict__ out)
{
    extern __shared__ __half smem[];
    const int tid = threadIdx.x;
    const int m0  = blockIdx.y * 64;
    const int n0  = blockIdx.x * 128;
    const int s   = blockIdx.z;
    const int kbeg = s * 1024;

    const float* pA[2]; int soffA[2];
    const float* pB[4]; int soffB[4];
#pragma unroll
    for (int i = 0; i < 2; ++i) {
        int c = tid + i * 256;
        int r = c >> 3, kc = c & 7;
        soffA[i] = r * ROWSTR + kc * 4;
        pA[i] = g_core + (size_t)(m0 + r) * TGT + kbeg + kc * 4;
    }
#pragma unroll
    for (int i = 0; i < 4; ++i) {
        int c = tid + i * 256;
        int r = c >> 3, kc = c & 7;
        soffB[i] = r * ROWSTR + kc * 4;
        pB[i] = Wout + (size_t)(n0 + r) * TGT + kbeg + kc * 4;
    }

    const unsigned sbase = (unsigned)__cvta_generic_to_shared(smem);
    const int lane = tid & 31, wid = tid >> 5;
    const int wm = wid >> 2, wn = wid & 3;

    float acc[2][4][4];
#pragma unroll
    for (int x = 0; x < 2; ++x)
#pragma unroll
        for (int y = 0; y < 4; ++y)
#pragma unroll
            for (int z = 0; z < 4; ++z) acc[x][y][z] = 0.f;

    const int arow = wm * 32 + (lane & 15);
    const int akk  = (lane >> 4) << 3;
    const int brow = wn * 32 + ((lane >> 4) << 3) + (lane & 7);
    const int bkk  = ((lane >> 3) & 1) << 3;

    float4 ra[2], rb[4];
#pragma unroll
    for (int i = 0; i < 2; ++i) ra[i] = *(const float4*)pA[i];
#pragma unroll
    for (int i = 0; i < 4; ++i) rb[i] = *(const float4*)pB[i];
    {
        __half* dst = smem;
#pragma unroll
        for (int i = 0; i < 2; ++i) {
            unsigned h0 = cvt2hi(ra[i].x, ra[i].y), h1 = cvt2hi(ra[i].z, ra[i].w);
            *(uint2*)(dst + OFF_AH + soffA[i]) = make_uint2(h0, h1);
        }
#pragma unroll
        for (int i = 0; i < 4; ++i) {
            unsigned h0, l0, h1, l1;
            cvt2(rb[i].x, rb[i].y, h0, l0); cvt2(rb[i].z, rb[i].w, h1, l1);
            *(uint2*)(dst + OFF_BH + soffB[i]) = make_uint2(h0, h1);
            *(uint2*)(dst + OFF_BL + soffB[i]) = make_uint2(l0, l1);
        }
    }
    __syncthreads();

    const int NT = 1024 / 32;
    int buf = 0;
    for (int t = 0; t < NT; ++t) {
        if (t + 1 < NT) {
#pragma unroll
            for (int i = 0; i < 2; ++i) ra[i] = *(const float4*)(pA[i] + (t + 1) * 32);
#pragma unroll
            for (int i = 0; i < 4; ++i) rb[i] = *(const float4*)(pB[i] + (t + 1) * 32);
        }
        const unsigned pb = sbase + (unsigned)(buf * BUFH * 2);
#pragma unroll
        for (int ks = 0; ks < 2; ++ks) {
            const int koff = ks * 16;
            unsigned ah[2][4], bh[2][4], bl[2][4];
#pragma unroll
            for (int mf = 0; mf < 2; ++mf) {
                unsigned aoff = (unsigned)(((arow + mf * 16) * ROWSTR + akk + koff) * 2);
                ldsm4(ah[mf], pb + OFF_AH * 2 + aoff);
            }
#pragma unroll
            for (int pr = 0; pr < 2; ++pr) {
                unsigned boff = (unsigned)(((brow + pr * 16) * ROWSTR + bkk + koff) * 2);
                ldsm4(bh[pr], pb + OFF_BH * 2 + boff);
                ldsm4(bl[pr], pb + OFF_BL * 2 + boff);
            }
#pragma unroll
            for (int mf = 0; mf < 2; ++mf)
#pragma unroll
                for (int nf = 0; nf < 4; ++nf) {
                    unsigned* bhp = &bh[nf >> 1][(nf & 1) * 2];
                    unsigned* blp = &bl[nf >> 1][(nf & 1) * 2];
                    MMA16816(acc[mf][nf], ah[mf], bhp);
                    MMA16816(acc[mf][nf], ah[mf], blp);
                }
        }
        if (t + 1 < NT) {
            __half* dst = smem + (buf ^ 1) * BUFH;
#pragma unroll
            for (int i = 0; i < 2; ++i) {
                unsigned h0 = cvt2hi(ra[i].x, ra[i].y), h1 = cvt2hi(ra[i].z, ra[i].w);
                *(uint2*)(dst + OFF_AH + soffA[i]) = make_uint2(h0, h1);
            }
#pragma unroll
            for (int i = 0; i < 4; ++i) {
                unsigned h0, l0, h1, l1;
                cvt2(rb[i].x, rb[i].y, h0, l0); cvt2(rb[i].z, rb[i].w, h1, l1);
                *(uint2*)(dst + OFF_BH + soffB[i]) = make_uint2(h0, h1);
                *(uint2*)(dst + OFF_BL + soffB[i]) = make_uint2(l0, l1);
            }
        }
        __syncthreads();
        buf ^= 1;
    }

    // epilogue: accumulate split-K partials straight into d_out
    const int mb = m0 + wm * 32 + (lane >> 2);
    const int cb = n0 + wn * 32 + (lane & 3) * 2;
#pragma unroll
    for (int mf = 0; mf < 2; ++mf)
#pragma unroll
        for (int nf = 0; nf < 4; ++nf)
#pragma unroll
            for (int h = 0; h < 2; ++h) {
                int m = mb + mf * 16 + h * 8;
                int col = cb + nf * 8;
                atomicAdd(&out[(size_t)m * HDIM + col],     acc[mf][nf][h * 2]);
                atomicAdd(&out[(size_t)m * HDIM + col + 1], acc[mf][nf][h * 2 + 1]);
            }
}

// =====================================================================
extern "C" void kernel_launch(void* const* d_in, const int* in_sizes, int n_in,
                              void* d_out, int out_size)
{
    (void)in_sizes; (void)n_in; (void)out_size;
    const float* hidden = (const float*)d_in[0];
    const float* Wqkv   = (const float*)d_in[1];
    const float* bqkv   = (const float*)d_in[2];
    const float* Wgate  = (const float*)d_in[3];
    const float* Walpha = (const float*)d_in[4];
    const float* Wbeta  = (const float*)d_in[5];
    const float* Wout   = (const float*)d_in[6];
    const float* ssa    = (const float*)d_in[7];
    const float* dtb    = (const float*)d_in[8];
    const float* normw  = (const float*)d_in[9];
    const float* convk  = (const float*)d_in[10];
    const float* sstate = (const float*)d_in[11];
    const float* convst = (const float*)d_in[12];
    float* out = (float*)d_out;

    cudaFuncSetAttribute(k_gemm1, cudaFuncAttributeMaxDynamicSharedMemorySize, SMEM_BYTES);
    cudaFuncSetAttribute(k_gemm2, cudaFuncAttributeMaxDynamicSharedMemorySize, SMEM_BYTES);

    k_gemm1<<<dim3(65, 4), 256, SMEM_BYTES>>>(hidden, Wqkv, Wgate, Walpha, Wbeta);
    k_fuse <<<NB, 256>>>(bqkv, convk, convst, ssa, dtb, normw, sstate, out);
    k_gemm2<<<dim3(16, 4, 4), 256, SMEM_BYTES>>>(Wout, out);
}